// round 6
// baseline (speedup 1.0000x reference)
#include <cuda_runtime.h>
#include <math.h>

#define Nn 50000
#define Ee 1600000
#define INF_FEATS 64
#define Hh 128
#define Ll 5
#define Gg 512
#define Cc 10

#define AS_STRIDE 132   // A-frag LDS conflict-free (4*lr+lc bijection)
#define BS_STRIDE 136   // B-frag LDS conflict-free (8*lc+lr bijection)
#define SL_STRIDE 386   // gate-slab stride (even -> float2-aligned, sheared banks)

// ---------------- scratch (device globals; no allocation allowed) ----------
__device__ float d_h[Nn * Hh];            // node state
__device__ float d_m[Nn * Hh];            // h @ W_l (compact)
__device__ float d_agg[Nn * Hh];          // gathered messages
__device__ float d_wihT[Hh * 3 * Hh];     // w_ih^T, pre-rounded to tf32 bits
__device__ float d_whhT[Hh * 3 * Hh];     // w_hh^T, pre-rounded to tf32 bits
__device__ float d_pooled[Gg * Hh];
__device__ float d_hid[Gg * 4 * Hh];
// CSR scratch
__device__ int   d_deg[Nn];
__device__ int   d_rowstart[Nn + 1];
__device__ int   d_cursor[Nn];
__device__ int   d_esrc[Ee];
__device__ float d_ews[Ee];

// ---------------- helpers ---------------------------------------------------
__device__ __forceinline__ float sigmoidf_(float x) {
    return 1.0f / (1.0f + expf(-x));
}

__device__ __forceinline__ unsigned f2tf32(float f) {
    unsigned u;
    asm("cvt.rna.tf32.f32 %0, %1;" : "=r"(u) : "f"(f));
    return u;
}

__device__ __forceinline__ void mma_tf32(float c[4], const unsigned a[4],
                                         const unsigned b[2]) {
    asm volatile(
        "mma.sync.aligned.m16n8k8.row.col.f32.tf32.tf32.f32 "
        "{%0,%1,%2,%3}, {%4,%5,%6,%7}, {%8,%9}, {%0,%1,%2,%3};"
        : "+f"(c[0]), "+f"(c[1]), "+f"(c[2]), "+f"(c[3])
        : "r"(a[0]), "r"(a[1]), "r"(a[2]), "r"(a[3]), "r"(b[0]), "r"(b[1]));
}

// ---------------- setup kernels ---------------------------------------------

__global__ void k_init_h(const float* __restrict__ x) {
    int i = blockIdx.x * blockDim.x + threadIdx.x;
    if (i >= Nn * Hh) return;
    int n = i >> 7, f = i & 127;
    d_h[i] = (f < INF_FEATS) ? x[n * INF_FEATS + f] : 0.0f;
}

// transpose + pre-round both GRU weight matrices to tf32 bit patterns
__global__ void k_prep_w(const float* __restrict__ wih,
                         const float* __restrict__ whh) {
    int i = blockIdx.x * blockDim.x + threadIdx.x;
    if (i >= 3 * Hh * Hh) return;
    int n = i / Hh, k = i % Hh;
    d_wihT[k * (3 * Hh) + n] = __uint_as_float(f2tf32(wih[i]));
    d_whhT[k * (3 * Hh) + n] = __uint_as_float(f2tf32(whh[i]));
}

// ---------------- CSR build --------------------------------------------------
__global__ void k_deg_zero() {
    int i = blockIdx.x * blockDim.x + threadIdx.x;
    if (i < Nn) d_deg[i] = 0;
}

__global__ void k_hist(const int* __restrict__ ei) {
    int e = blockIdx.x * blockDim.x + threadIdx.x;
    if (e < Ee) atomicAdd(&d_deg[ei[Ee + e]], 1);
}

__global__ void k_scan() {
    __shared__ int sp[1024];
    const int CH = (Nn + 1023) / 1024;
    int t = threadIdx.x;
    int base = t * CH;
    int s = 0;
    for (int i = 0; i < CH; i++) {
        int idx = base + i;
        if (idx < Nn) s += d_deg[idx];
    }
    sp[t] = s;
    __syncthreads();
    for (int d = 1; d < 1024; d <<= 1) {
        int add = (t >= d) ? sp[t - d] : 0;
        __syncthreads();
        sp[t] += add;
        __syncthreads();
    }
    int off = sp[t] - s;
    for (int i = 0; i < CH; i++) {
        int idx = base + i;
        if (idx < Nn) {
            d_rowstart[idx] = off;
            d_cursor[idx] = off;
            off += d_deg[idx];
        }
    }
    if (t == 1023) d_rowstart[Nn] = off;
}

__global__ void k_scatter(const int* __restrict__ ei, const float* __restrict__ ew) {
    int e = blockIdx.x * blockDim.x + threadIdx.x;
    if (e >= Ee) return;
    int dst = ei[Ee + e];
    int pos = atomicAdd(&d_cursor[dst], 1);
    d_esrc[pos] = ei[e];
    d_ews[pos] = ew[e];
}

// ---------------- GEMM (tf32 tensor cores): m = h @ W_l ----------------------
__global__ void k_gemm_tc(const float* __restrict__ A, const float* __restrict__ B,
                          float* __restrict__ C, int M, int Nw) {
    extern __shared__ float sm[];
    float* As = sm;
    float* Bs = sm + 128 * AS_STRIDE;

    int m0 = blockIdx.x * 128;
    int n0 = blockIdx.y * 128;
    int tid = threadIdx.x;

    #pragma unroll
    for (int i = 0; i < 16; i++) {
        int e = tid + i * 256;
        int r = e >> 5, c4 = e & 31;
        float4 v = make_float4(0.f, 0.f, 0.f, 0.f);
        if (m0 + r < M)
            v = reinterpret_cast<const float4*>(A + (size_t)(m0 + r) * 128)[c4];
        unsigned* dst = reinterpret_cast<unsigned*>(As + r * AS_STRIDE + c4 * 4);
        dst[0] = f2tf32(v.x); dst[1] = f2tf32(v.y);
        dst[2] = f2tf32(v.z); dst[3] = f2tf32(v.w);
    }
    #pragma unroll
    for (int i = 0; i < 16; i++) {
        int e = tid + i * 256;
        int r = e >> 5, c4 = e & 31;
        float4 v = reinterpret_cast<const float4*>(B + (size_t)r * Nw + n0)[c4];
        unsigned* dst = reinterpret_cast<unsigned*>(Bs + r * BS_STRIDE + c4 * 4);
        dst[0] = f2tf32(v.x); dst[1] = f2tf32(v.y);
        dst[2] = f2tf32(v.z); dst[3] = f2tf32(v.w);
    }
    __syncthreads();

    int wid = tid >> 5, lane = tid & 31;
    int wm = (wid & 3) * 32;
    int wn = (wid >> 2) * 64;
    int lr = lane >> 2;
    int lc = lane & 3;

    float acc[2][8][4];
    #pragma unroll
    for (int mt = 0; mt < 2; mt++)
        #pragma unroll
        for (int nt = 0; nt < 8; nt++)
            #pragma unroll
            for (int q = 0; q < 4; q++) acc[mt][nt][q] = 0.0f;

    const unsigned* Asu = reinterpret_cast<const unsigned*>(As);
    const unsigned* Bsu = reinterpret_cast<const unsigned*>(Bs);

    #pragma unroll
    for (int k0 = 0; k0 < 128; k0 += 8) {
        unsigned a[2][4], b[8][2];
        #pragma unroll
        for (int mt = 0; mt < 2; mt++) {
            const unsigned* ap = Asu + (wm + mt * 16 + lr) * AS_STRIDE + k0 + lc;
            a[mt][0] = ap[0];
            a[mt][1] = ap[8 * AS_STRIDE];
            a[mt][2] = ap[4];
            a[mt][3] = ap[8 * AS_STRIDE + 4];
        }
        #pragma unroll
        for (int nt = 0; nt < 8; nt++) {
            const unsigned* bp = Bsu + (k0 + lc) * BS_STRIDE + wn + nt * 8 + lr;
            b[nt][0] = bp[0];
            b[nt][1] = bp[4 * BS_STRIDE];
        }
        #pragma unroll
        for (int mt = 0; mt < 2; mt++)
            #pragma unroll
            for (int nt = 0; nt < 8; nt++)
                mma_tf32(acc[mt][nt], a[mt], b[nt]);
    }

    #pragma unroll
    for (int mt = 0; mt < 2; mt++) {
        #pragma unroll
        for (int nt = 0; nt < 8; nt++) {
            int row = m0 + wm + mt * 16 + lr;
            int col = n0 + wn + nt * 8 + lc * 2;
            if (row < M) {
                float2 v = make_float2(acc[mt][nt][0], acc[mt][nt][1]);
                *reinterpret_cast<float2*>(C + (size_t)row * Nw + col) = v;
            }
            if (row + 8 < M) {
                float2 v = make_float2(acc[mt][nt][2], acc[mt][nt][3]);
                *reinterpret_cast<float2*>(C + (size_t)(row + 8) * Nw + col) = v;
            }
        }
    }
}

// ---------------- CSR aggregation: warp per node ------------------------------
__global__ void k_agg() {
    int warp = (blockIdx.x * blockDim.x + threadIdx.x) >> 5;
    if (warp >= Nn) return;
    int lane = threadIdx.x & 31;
    int beg = d_rowstart[warp];
    int end = d_rowstart[warp + 1];
    float4 acc = make_float4(0.f, 0.f, 0.f, 0.f);
    for (int base = beg; base < end; base += 32) {
        int idx = base + lane;
        int sid = 0;
        float w = 0.0f;
        if (idx < end) { sid = d_esrc[idx]; w = d_ews[idx]; }
        int cnt = min(32, end - base);
        #pragma unroll 4
        for (int j = 0; j < cnt; j++) {
            int s = __shfl_sync(0xffffffff, sid, j);
            float wj = __shfl_sync(0xffffffff, w, j);
            float4 v = *reinterpret_cast<const float4*>(
                d_m + (size_t)s * 128 + lane * 4);
            acc.x = fmaf(v.x, wj, acc.x);
            acc.y = fmaf(v.y, wj, acc.y);
            acc.z = fmaf(v.z, wj, acc.z);
            acc.w = fmaf(v.w, wj, acc.w);
        }
    }
    *reinterpret_cast<float4*>(d_agg + (size_t)warp * 128 + lane * 4) = acc;
}

// ---------------- fused gi-GEMM + gh-GEMM + GRU -------------------------------
// Per block: 32 rows. gi = agg@wihT + b_ih, gh = h@whhT + b_hh (tf32 MMA, B
// streamed from L2), gate slabs staged in smem, GRU applied, h written.
__global__ void __launch_bounds__(256, 1)
k_fused_gru(const float* __restrict__ b_ih, const float* __restrict__ b_hh) {
    extern __shared__ float sm[];
    float* As1 = sm;                         // agg tile  [32][AS_STRIDE] (tf32)
    float* As2 = sm + 32 * AS_STRIDE;        // h tile    [32][AS_STRIDE] (tf32)
    float* Sgi = sm + 2 * 32 * AS_STRIDE;    // gi slab   [32][SL_STRIDE]
    float* Sgh = Sgi + 32 * SL_STRIDE;       // gh slab   [32][SL_STRIDE]

    int n0 = blockIdx.x * 32;
    int tid = threadIdx.x;

    // load A tiles (32x128 each), convert to tf32
    #pragma unroll
    for (int i = 0; i < 4; i++) {
        int e = tid + i * 256;          // float4 slot 0..1023
        int r = e >> 5, c4 = e & 31;
        float4 va = make_float4(0.f, 0.f, 0.f, 0.f);
        float4 vh = make_float4(0.f, 0.f, 0.f, 0.f);
        if (n0 + r < Nn) {
            va = reinterpret_cast<const float4*>(d_agg + (size_t)(n0 + r) * 128)[c4];
            vh = reinterpret_cast<const float4*>(d_h   + (size_t)(n0 + r) * 128)[c4];
        }
        unsigned* d1 = reinterpret_cast<unsigned*>(As1 + r * AS_STRIDE + c4 * 4);
        unsigned* d2 = reinterpret_cast<unsigned*>(As2 + r * AS_STRIDE + c4 * 4);
        d1[0] = f2tf32(va.x); d1[1] = f2tf32(va.y);
        d1[2] = f2tf32(va.z); d1[3] = f2tf32(va.w);
        d2[0] = f2tf32(vh.x); d2[1] = f2tf32(vh.y);
        d2[2] = f2tf32(vh.z); d2[3] = f2tf32(vh.w);
    }
    __syncthreads();

    int wid = tid >> 5, lane = tid & 31;
    int wcol = wid * 48;            // warp's 48-col slice of 384
    int lr = lane >> 2;
    int lc = lane & 3;

    const unsigned* As1u = reinterpret_cast<const unsigned*>(As1);
    const unsigned* As2u = reinterpret_cast<const unsigned*>(As2);
    const unsigned* Bih = reinterpret_cast<const unsigned*>(d_wihT);
    const unsigned* Bhh = reinterpret_cast<const unsigned*>(d_whhT);

    // ---- GEMM 1: gi = agg @ wihT ----
    {
        float acc[2][6][4];
        #pragma unroll
        for (int mt = 0; mt < 2; mt++)
            #pragma unroll
            for (int nt = 0; nt < 6; nt++)
                #pragma unroll
                for (int q = 0; q < 4; q++) acc[mt][nt][q] = 0.0f;

        #pragma unroll
        for (int k0 = 0; k0 < 128; k0 += 8) {
            unsigned a[2][4], b[6][2];
            #pragma unroll
            for (int mt = 0; mt < 2; mt++) {
                const unsigned* ap = As1u + (mt * 16 + lr) * AS_STRIDE + k0 + lc;
                a[mt][0] = ap[0];
                a[mt][1] = ap[8 * AS_STRIDE];
                a[mt][2] = ap[4];
                a[mt][3] = ap[8 * AS_STRIDE + 4];
            }
            #pragma unroll
            for (int nt = 0; nt < 6; nt++) {
                const unsigned* bp = Bih + (size_t)(k0 + lc) * 384 + wcol + nt * 8 + lr;
                b[nt][0] = bp[0];
                b[nt][1] = bp[4 * 384];
            }
            #pragma unroll
            for (int mt = 0; mt < 2; mt++)
                #pragma unroll
                for (int nt = 0; nt < 6; nt++)
                    mma_tf32(acc[mt][nt], a[mt], b[nt]);
        }
        #pragma unroll
        for (int mt = 0; mt < 2; mt++)
            #pragma unroll
            for (int nt = 0; nt < 6; nt++) {
                int rw = mt * 16 + lr;
                int col = wcol + nt * 8 + lc * 2;
                float b0 = b_ih[col], b1 = b_ih[col + 1];
                *reinterpret_cast<float2*>(Sgi + rw * SL_STRIDE + col) =
                    make_float2(acc[mt][nt][0] + b0, acc[mt][nt][1] + b1);
                *reinterpret_cast<float2*>(Sgi + (rw + 8) * SL_STRIDE + col) =
                    make_float2(acc[mt][nt][2] + b0, acc[mt][nt][3] + b1);
            }
    }

    // ---- GEMM 2: gh = h @ whhT ----
    {
        float acc[2][6][4];
        #pragma unroll
        for (int mt = 0; mt < 2; mt++)
            #pragma unroll
            for (int nt = 0; nt < 6; nt++)
                #pragma unroll
                for (int q = 0; q < 4; q++) acc[mt][nt][q] = 0.0f;

        #pragma unroll
        for (int k0 = 0; k0 < 128; k0 += 8) {
            unsigned a[2][4], b[6][2];
            #pragma unroll
            for (int mt = 0; mt < 2; mt++) {
                const unsigned* ap = As2u + (mt * 16 + lr) * AS_STRIDE + k0 + lc;
                a[mt][0] = ap[0];
                a[mt][1] = ap[8 * AS_STRIDE];
                a[mt][2] = ap[4];
                a[mt][3] = ap[8 * AS_STRIDE + 4];
            }
            #pragma unroll
            for (int nt = 0; nt < 6; nt++) {
                const unsigned* bp = Bhh + (size_t)(k0 + lc) * 384 + wcol + nt * 8 + lr;
                b[nt][0] = bp[0];
                b[nt][1] = bp[4 * 384];
            }
            #pragma unroll
            for (int mt = 0; mt < 2; mt++)
                #pragma unroll
                for (int nt = 0; nt < 6; nt++)
                    mma_tf32(acc[mt][nt], a[mt], b[nt]);
        }
        #pragma unroll
        for (int mt = 0; mt < 2; mt++)
            #pragma unroll
            for (int nt = 0; nt < 6; nt++) {
                int rw = mt * 16 + lr;
                int col = wcol + nt * 8 + lc * 2;
                float b0 = b_hh[col], b1 = b_hh[col + 1];
                *reinterpret_cast<float2*>(Sgh + rw * SL_STRIDE + col) =
                    make_float2(acc[mt][nt][0] + b0, acc[mt][nt][1] + b1);
                *reinterpret_cast<float2*>(Sgh + (rw + 8) * SL_STRIDE + col) =
                    make_float2(acc[mt][nt][2] + b0, acc[mt][nt][3] + b1);
            }
    }
    __syncthreads();

    // ---- GRU elementwise: thread -> (row = tid>>3, f = (tid&7)+8i) ----
    int r = tid >> 3;
    int fb = tid & 7;
    int row = n0 + r;
    if (row < Nn) {
        const float* gi = Sgi + r * SL_STRIDE;
        const float* gh = Sgh + r * SL_STRIDE;
        float* hrow = d_h + (size_t)row * 128;
        #pragma unroll
        for (int i = 0; i < 16; i++) {
            int f = fb + 8 * i;
            float rr = sigmoidf_(gi[f] + gh[f]);
            float zz = sigmoidf_(gi[128 + f] + gh[128 + f]);
            float nn = tanhf(gi[256 + f] + rr * gh[256 + f]);
            float ho = hrow[f];
            hrow[f] = (1.0f - zz) * nn + zz * ho;
        }
    }
}

// ---------------- pooling + MLP ----------------------------------------------
__global__ void k_pool_init() {
    int i = blockIdx.x * blockDim.x + threadIdx.x;
    if (i < Gg * Hh) d_pooled[i] = -INFINITY;
}

__global__ void k_pool(const int* __restrict__ batch) {
    int i = blockIdx.x * blockDim.x + threadIdx.x;
    if (i >= Nn * Hh) return;
    int n = i >> 7, f = i & 127;
    float v = d_h[i];
    int g = batch[n];
    float* addr = &d_pooled[g * Hh + f];
    if (v >= 0.0f)
        atomicMax(reinterpret_cast<int*>(addr), __float_as_int(v));
    else
        atomicMin(reinterpret_cast<unsigned*>(addr), __float_as_uint(v));
}

__global__ void k_mlp1(const float* __restrict__ w, const float* __restrict__ b) {
    __shared__ float p[Hh];
    int g = blockIdx.x;
    p[threadIdx.x] = d_pooled[g * Hh + threadIdx.x];
    __syncthreads();
    for (int o = threadIdx.x; o < 4 * Hh; o += blockDim.x) {
        const float* wr = w + (size_t)o * Hh;
        float s = b[o];
        #pragma unroll 4
        for (int k = 0; k < Hh; k++) s = fmaf(p[k], wr[k], s);
        d_hid[g * 4 * Hh + o] = fmaxf(s, 0.0f);
    }
}

__global__ void k_mlp2(const float* __restrict__ w, const float* __restrict__ b,
                       float* __restrict__ out) {
    __shared__ float hsh[4 * Hh];
    int g = blockIdx.x;
    for (int i = threadIdx.x; i < 4 * Hh; i += blockDim.x)
        hsh[i] = d_hid[g * 4 * Hh + i];
    __syncthreads();
    int warp = threadIdx.x >> 5, lane = threadIdx.x & 31;
    if (warp < Cc) {
        const float* wr = w + (size_t)warp * (4 * Hh);
        float s = 0.0f;
        for (int k = lane; k < 4 * Hh; k += 32) s = fmaf(hsh[k], wr[k], s);
        #pragma unroll
        for (int off = 16; off; off >>= 1)
            s += __shfl_down_sync(0xffffffff, s, off);
        if (lane == 0) out[g * Cc + warp] = s + b[warp];
    }
}

// ---------------- launch ------------------------------------------------------
extern "C" void kernel_launch(void* const* d_in, const int* in_sizes, int n_in,
                              void* d_out, int out_size) {
    const float* x     = (const float*)d_in[0];
    const int*   ei    = (const int*)  d_in[1];
    const int*   batch = (const int*)  d_in[2];
    const float* ew    = (const float*)d_in[3];
    const float* weight= (const float*)d_in[4];
    const float* w_ih  = (const float*)d_in[5];
    const float* w_hh  = (const float*)d_in[6];
    const float* b_ih  = (const float*)d_in[7];
    const float* b_hh  = (const float*)d_in[8];
    const float* d1w   = (const float*)d_in[9];
    const float* d1b   = (const float*)d_in[10];
    const float* d2w   = (const float*)d_in[11];
    const float* d2b   = (const float*)d_in[12];
    float* out = (float*)d_out;

    float *ph, *pm;
    cudaGetSymbolAddress((void**)&ph, d_h);
    cudaGetSymbolAddress((void**)&pm, d_m);

    const int GEMM_SMEM  = (128 * AS_STRIDE + 128 * BS_STRIDE) * (int)sizeof(float);
    const int FUSED_SMEM = (2 * 32 * AS_STRIDE + 2 * 32 * SL_STRIDE) * (int)sizeof(float);
    cudaFuncSetAttribute(k_gemm_tc, cudaFuncAttributeMaxDynamicSharedMemorySize,
                         GEMM_SMEM);
    cudaFuncSetAttribute(k_fused_gru, cudaFuncAttributeMaxDynamicSharedMemorySize,
                         FUSED_SMEM);

    const int NH = Nn * Hh;
    // setup
    k_init_h<<<(NH + 255) / 256, 256>>>(x);
    k_prep_w<<<(3 * Hh * Hh + 255) / 256, 256>>>(w_ih, w_hh);
    // CSR build
    k_deg_zero<<<(Nn + 255) / 256, 256>>>();
    k_hist<<<(Ee + 255) / 256, 256>>>(ei);
    k_scan<<<1, 1024>>>();
    k_scatter<<<(Ee + 255) / 256, 256>>>(ei, ew);

    const int MB = (Nn + 127) / 128;      // 391
    const int FB = (Nn + 31) / 32;        // 1563
    for (int l = 0; l < Ll; l++) {
        // m = h @ weight[l]   (compact [N,128])
        k_gemm_tc<<<dim3(MB, 1), 256, GEMM_SMEM>>>(
            ph, weight + (size_t)l * Hh * Hh, pm, Nn, Hh);
        // agg = CSR gather of m[src]*w
        k_agg<<<(Nn * 32 + 255) / 256, 256>>>();
        // h = GRU(agg @ wihT + b_ih, h @ whhT + b_hh, h)   — fully fused
        k_fused_gru<<<FB, 256, FUSED_SMEM>>>(b_ih, b_hh);
    }

    k_pool_init<<<(Gg * Hh + 255) / 256, 256>>>();
    k_pool<<<(NH + 255) / 256, 256>>>(batch);
    k_mlp1<<<Gg, Hh>>>(d1w, d1b);
    k_mlp2<<<Gg, 320>>>(d2w, d2b, out);
}

// round 8
// speedup vs baseline: 1.4663x; 1.4663x over previous
#include <cuda_runtime.h>
#include <math.h>

#define Nn 50000
#define Ee 1600000
#define INF_FEATS 64
#define Hh 128
#define Ll 5
#define Gg 512
#define Cc 10

#define AS_STRIDE 68    // 64 + 4 pad  -> A-frag LDS conflict-free (4*lr+lc)
#define BS_STRIDE 136   // 128 + 8 pad -> B-frag LDS conflict-free (8*lc+lr)

// ---------------- scratch (device globals; no allocation allowed) ----------
__device__ float d_h[Nn * Hh];            // node state
__device__ float d_mgh[Nn * 512];         // [m (128) | gh (384)] fused GEMM out
__device__ float d_agg[Nn * Hh];          // gathered messages
__device__ float d_gi[Nn * 3 * Hh];       // agg @ w_ih^T
__device__ float d_wihT[Hh * 3 * Hh];     // w_ih transposed [128,384]
__device__ float d_Bcat[Ll * Hh * 512];   // per-layer [W_l | w_hh^T]  [128,512]
__device__ float d_bcat[512];             // [0 | b_hh]
__device__ float d_pooled[Gg * Hh];
__device__ float d_hid[Gg * 4 * Hh];
// CSR scratch
__device__ int   d_deg[Nn];
__device__ int   d_rowstart[Nn + 1];
__device__ int   d_cursor[Nn];
__device__ int   d_esrc[Ee];
__device__ float d_ews[Ee];

// ---------------- helpers ---------------------------------------------------
__device__ __forceinline__ float sigmoidf_(float x) {
    return 1.0f / (1.0f + expf(-x));
}

__device__ __forceinline__ unsigned f2tf32(float f) {
    unsigned u;
    asm("cvt.rna.tf32.f32 %0, %1;" : "=r"(u) : "f"(f));
    return u;
}

__device__ __forceinline__ void mma_tf32(float c[4], const unsigned a[4],
                                         const unsigned b[2]) {
    asm volatile(
        "mma.sync.aligned.m16n8k8.row.col.f32.tf32.tf32.f32 "
        "{%0,%1,%2,%3}, {%4,%5,%6,%7}, {%8,%9}, {%0,%1,%2,%3};"
        : "+f"(c[0]), "+f"(c[1]), "+f"(c[2]), "+f"(c[3])
        : "r"(a[0]), "r"(a[1]), "r"(a[2]), "r"(a[3]), "r"(b[0]), "r"(b[1]));
}

// ---------------- setup kernels ---------------------------------------------

__global__ void k_init_h(const float* __restrict__ x) {
    int i = blockIdx.x * blockDim.x + threadIdx.x;
    if (i >= Nn * Hh) return;
    int n = i >> 7, f = i & 127;
    d_h[i] = (f < INF_FEATS) ? x[n * INF_FEATS + f] : 0.0f;
}

// wihT[k][n] = w_ih[n][k]
__global__ void k_transpose_wih(const float* __restrict__ wih) {
    int i = blockIdx.x * blockDim.x + threadIdx.x;
    if (i >= 3 * Hh * Hh) return;
    int n = i / Hh, k = i % Hh;
    d_wihT[k * (3 * Hh) + n] = wih[i];
}

// Bcat[l][k][c] = (c<128) ? weight[l][k][c] : w_hh[c-128][k];  bcat too
__global__ void k_build_bcat(const float* __restrict__ weight,
                             const float* __restrict__ whh,
                             const float* __restrict__ bhh) {
    int i = blockIdx.x * blockDim.x + threadIdx.x;
    if (i < 512) d_bcat[i] = (i < 128) ? 0.0f : bhh[i - 128];
    if (i >= Ll * Hh * 512) return;
    int l = i / (Hh * 512);
    int r = i % (Hh * 512);
    int k = r / 512, c = r % 512;
    d_Bcat[i] = (c < 128) ? weight[(size_t)l * Hh * Hh + k * Hh + c]
                          : whh[(size_t)(c - 128) * Hh + k];
}

// ---------------- CSR build --------------------------------------------------
__global__ void k_deg_zero() {
    int i = blockIdx.x * blockDim.x + threadIdx.x;
    if (i < Nn) d_deg[i] = 0;
}

__global__ void k_hist(const int* __restrict__ ei) {
    int e = blockIdx.x * blockDim.x + threadIdx.x;
    if (e < Ee) atomicAdd(&d_deg[ei[Ee + e]], 1);
}

__global__ void k_scan() {
    __shared__ int sp[1024];
    const int CH = (Nn + 1023) / 1024;
    int t = threadIdx.x;
    int base = t * CH;
    int s = 0;
    for (int i = 0; i < CH; i++) {
        int idx = base + i;
        if (idx < Nn) s += d_deg[idx];
    }
    sp[t] = s;
    __syncthreads();
    for (int d = 1; d < 1024; d <<= 1) {
        int add = (t >= d) ? sp[t - d] : 0;
        __syncthreads();
        sp[t] += add;
        __syncthreads();
    }
    int off = sp[t] - s;
    for (int i = 0; i < CH; i++) {
        int idx = base + i;
        if (idx < Nn) {
            d_rowstart[idx] = off;
            d_cursor[idx] = off;
            off += d_deg[idx];
        }
    }
    if (t == 1023) d_rowstart[Nn] = off;
}

__global__ void k_scatter(const int* __restrict__ ei, const float* __restrict__ ew) {
    int e = blockIdx.x * blockDim.x + threadIdx.x;
    if (e >= Ee) return;
    int dst = ei[Ee + e];
    int pos = atomicAdd(&d_cursor[dst], 1);
    d_esrc[pos] = ei[e];
    d_ews[pos] = ew[e];
}

// ---------------- GEMM (tf32 tensor cores, K split in two 64-slabs) ----------
// C[M,Nw] = A[M,128] @ B[128,Nw] (+bias). 128x128 tile, 256 thr, warp 32x64.
// smem halved vs monolithic-K -> 2 CTAs/SM co-resident hide load phases.
__global__ void k_gemm_tc(const float* __restrict__ A, const float* __restrict__ B,
                          const float* __restrict__ bias, float* __restrict__ C,
                          int M, int Nw) {
    extern __shared__ float sm[];
    float* As = sm;                          // [128][AS_STRIDE] (64 K-cols)
    float* Bs = sm + 128 * AS_STRIDE;        // [64][BS_STRIDE]  (64 K-rows)

    int m0 = blockIdx.x * 128;
    int n0 = blockIdx.y * 128;
    int tid = threadIdx.x;

    int wid = tid >> 5, lane = tid & 31;
    int wm = (wid & 3) * 32;
    int wn = (wid >> 2) * 64;
    int lr = lane >> 2;
    int lc = lane & 3;

    float acc[2][8][4];
    #pragma unroll
    for (int mt = 0; mt < 2; mt++)
        #pragma unroll
        for (int nt = 0; nt < 8; nt++)
            #pragma unroll
            for (int q = 0; q < 4; q++) acc[mt][nt][q] = 0.0f;

    const unsigned* Asu = reinterpret_cast<const unsigned*>(As);
    const unsigned* Bsu = reinterpret_cast<const unsigned*>(Bs);

    #pragma unroll
    for (int s = 0; s < 2; s++) {
        // load A slab: rows m0..m0+127, K cols [64s, 64s+64)
        #pragma unroll
        for (int i = 0; i < 8; i++) {
            int e = tid + i * 256;            // float4 slot 0..2047
            int r = e >> 4, c4 = e & 15;      // 16 float4 per row
            float4 v = make_float4(0.f, 0.f, 0.f, 0.f);
            if (m0 + r < M)
                v = reinterpret_cast<const float4*>(
                        A + (size_t)(m0 + r) * 128 + s * 64)[c4];
            unsigned* dst = reinterpret_cast<unsigned*>(As + r * AS_STRIDE + c4 * 4);
            dst[0] = f2tf32(v.x); dst[1] = f2tf32(v.y);
            dst[2] = f2tf32(v.z); dst[3] = f2tf32(v.w);
        }
        // load B slab: K rows [64s, 64s+64), cols n0..n0+127
        #pragma unroll
        for (int i = 0; i < 8; i++) {
            int e = tid + i * 256;
            int r = e >> 5, c4 = e & 31;      // 32 float4 per row
            float4 v = reinterpret_cast<const float4*>(
                           B + (size_t)(s * 64 + r) * Nw + n0)[c4];
            unsigned* dst = reinterpret_cast<unsigned*>(Bs + r * BS_STRIDE + c4 * 4);
            dst[0] = f2tf32(v.x); dst[1] = f2tf32(v.y);
            dst[2] = f2tf32(v.z); dst[3] = f2tf32(v.w);
        }
        __syncthreads();

        #pragma unroll
        for (int k0 = 0; k0 < 64; k0 += 8) {
            unsigned a[2][4], b[8][2];
            #pragma unroll
            for (int mt = 0; mt < 2; mt++) {
                const unsigned* ap = Asu + (wm + mt * 16 + lr) * AS_STRIDE + k0 + lc;
                a[mt][0] = ap[0];
                a[mt][1] = ap[8 * AS_STRIDE];
                a[mt][2] = ap[4];
                a[mt][3] = ap[8 * AS_STRIDE + 4];
            }
            #pragma unroll
            for (int nt = 0; nt < 8; nt++) {
                const unsigned* bp = Bsu + (k0 + lc) * BS_STRIDE + wn + nt * 8 + lr;
                b[nt][0] = bp[0];
                b[nt][1] = bp[4 * BS_STRIDE];
            }
            #pragma unroll
            for (int mt = 0; mt < 2; mt++)
                #pragma unroll
                for (int nt = 0; nt < 8; nt++)
                    mma_tf32(acc[mt][nt], a[mt], b[nt]);
        }
        __syncthreads();
    }

    #pragma unroll
    for (int mt = 0; mt < 2; mt++) {
        #pragma unroll
        for (int nt = 0; nt < 8; nt++) {
            int row = m0 + wm + mt * 16 + lr;
            int col = n0 + wn + nt * 8 + lc * 2;
            float b0 = bias ? bias[col] : 0.0f;
            float b1 = bias ? bias[col + 1] : 0.0f;
            if (row < M) {
                float2 v = make_float2(acc[mt][nt][0] + b0, acc[mt][nt][1] + b1);
                *reinterpret_cast<float2*>(C + (size_t)row * Nw + col) = v;
            }
            if (row + 8 < M) {
                float2 v = make_float2(acc[mt][nt][2] + b0, acc[mt][nt][3] + b1);
                *reinterpret_cast<float2*>(C + (size_t)(row + 8) * Nw + col) = v;
            }
        }
    }
}

// ---------------- CSR aggregation: warp per node ------------------------------
// agg[n] = sum_{e in in(n)} m[src(e)] * w(e);  m = d_mgh[:, 0:128] (stride 512)
__global__ void k_agg() {
    int warp = (blockIdx.x * blockDim.x + threadIdx.x) >> 5;
    if (warp >= Nn) return;
    int lane = threadIdx.x & 31;
    int beg = d_rowstart[warp];
    int end = d_rowstart[warp + 1];
    float4 acc = make_float4(0.f, 0.f, 0.f, 0.f);
    for (int base = beg; base < end; base += 32) {
        int idx = base + lane;
        int sid = 0;
        float w = 0.0f;
        if (idx < end) { sid = d_esrc[idx]; w = d_ews[idx]; }
        int cnt = min(32, end - base);
        #pragma unroll 4
        for (int j = 0; j < cnt; j++) {
            int s = __shfl_sync(0xffffffff, sid, j);
            float wj = __shfl_sync(0xffffffff, w, j);
            float4 v = *reinterpret_cast<const float4*>(
                d_mgh + (size_t)s * 512 + lane * 4);
            acc.x = fmaf(v.x, wj, acc.x);
            acc.y = fmaf(v.y, wj, acc.y);
            acc.z = fmaf(v.z, wj, acc.z);
            acc.w = fmaf(v.w, wj, acc.w);
        }
    }
    *reinterpret_cast<float4*>(d_agg + (size_t)warp * 128 + lane * 4) = acc;
}

// ---------------- GRU --------------------------------------------------------
__global__ void k_gru() {
    int n = blockIdx.x;
    int f = threadIdx.x;
    const float* gi = d_gi + (size_t)n * 384;
    const float* gh = d_mgh + (size_t)n * 512 + 128;
    float r  = sigmoidf_(gi[f] + gh[f]);
    float z  = sigmoidf_(gi[128 + f] + gh[128 + f]);
    float nn = tanhf(gi[256 + f] + r * gh[256 + f]);
    float ho = d_h[(size_t)n * 128 + f];
    d_h[(size_t)n * 128 + f] = (1.0f - z) * nn + z * ho;
}

// ---------------- pooling + MLP ----------------------------------------------
__global__ void k_pool_init() {
    int i = blockIdx.x * blockDim.x + threadIdx.x;
    if (i < Gg * Hh) d_pooled[i] = -INFINITY;
}

__global__ void k_pool(const int* __restrict__ batch) {
    int i = blockIdx.x * blockDim.x + threadIdx.x;
    if (i >= Nn * Hh) return;
    int n = i >> 7, f = i & 127;
    float v = d_h[i];
    int g = batch[n];
    float* addr = &d_pooled[g * Hh + f];
    if (v >= 0.0f)
        atomicMax(reinterpret_cast<int*>(addr), __float_as_int(v));
    else
        atomicMin(reinterpret_cast<unsigned*>(addr), __float_as_uint(v));
}

__global__ void k_mlp1(const float* __restrict__ w, const float* __restrict__ b) {
    __shared__ float p[Hh];
    int g = blockIdx.x;
    p[threadIdx.x] = d_pooled[g * Hh + threadIdx.x];
    __syncthreads();
    for (int o = threadIdx.x; o < 4 * Hh; o += blockDim.x) {
        const float* wr = w + (size_t)o * Hh;
        float s = b[o];
        #pragma unroll 4
        for (int k = 0; k < Hh; k++) s = fmaf(p[k], wr[k], s);
        d_hid[g * 4 * Hh + o] = fmaxf(s, 0.0f);
    }
}

__global__ void k_mlp2(const float* __restrict__ w, const float* __restrict__ b,
                       float* __restrict__ out) {
    __shared__ float hsh[4 * Hh];
    int g = blockIdx.x;
    for (int i = threadIdx.x; i < 4 * Hh; i += blockDim.x)
        hsh[i] = d_hid[g * 4 * Hh + i];
    __syncthreads();
    int warp = threadIdx.x >> 5, lane = threadIdx.x & 31;
    if (warp < Cc) {
        const float* wr = w + (size_t)warp * (4 * Hh);
        float s = 0.0f;
        for (int k = lane; k < 4 * Hh; k += 32) s = fmaf(hsh[k], wr[k], s);
        #pragma unroll
        for (int off = 16; off; off >>= 1)
            s += __shfl_down_sync(0xffffffff, s, off);
        if (lane == 0) out[g * Cc + warp] = s + b[warp];
    }
}

// ---------------- launch ------------------------------------------------------
extern "C" void kernel_launch(void* const* d_in, const int* in_sizes, int n_in,
                              void* d_out, int out_size) {
    const float* x     = (const float*)d_in[0];
    const int*   ei    = (const int*)  d_in[1];
    const int*   batch = (const int*)  d_in[2];
    const float* ew    = (const float*)d_in[3];
    const float* weight= (const float*)d_in[4];
    const float* w_ih  = (const float*)d_in[5];
    const float* w_hh  = (const float*)d_in[6];
    const float* b_ih  = (const float*)d_in[7];
    const float* b_hh  = (const float*)d_in[8];
    const float* d1w   = (const float*)d_in[9];
    const float* d1b   = (const float*)d_in[10];
    const float* d2w   = (const float*)d_in[11];
    const float* d2b   = (const float*)d_in[12];
    float* out = (float*)d_out;

    float *ph, *pmgh, *pagg, *pgi, *pwihT, *pBcat, *pbcat;
    cudaGetSymbolAddress((void**)&ph,    d_h);
    cudaGetSymbolAddress((void**)&pmgh,  d_mgh);
    cudaGetSymbolAddress((void**)&pagg,  d_agg);
    cudaGetSymbolAddress((void**)&pgi,   d_gi);
    cudaGetSymbolAddress((void**)&pwihT, d_wihT);
    cudaGetSymbolAddress((void**)&pBcat, d_Bcat);
    cudaGetSymbolAddress((void**)&pbcat, d_bcat);

    const int GEMM_SMEM = (128 * AS_STRIDE + 64 * BS_STRIDE) * (int)sizeof(float);
    cudaFuncSetAttribute(k_gemm_tc, cudaFuncAttributeMaxDynamicSharedMemorySize,
                         GEMM_SMEM);

    const int NH = Nn * Hh;
    // setup
    k_init_h<<<(NH + 255) / 256, 256>>>(x);
    k_transpose_wih<<<(3 * Hh * Hh + 255) / 256, 256>>>(w_ih);
    k_build_bcat<<<(Ll * Hh * 512 + 255) / 256, 256>>>(weight, w_hh, b_hh);
    // CSR build
    k_deg_zero<<<(Nn + 255) / 256, 256>>>();
    k_hist<<<(Ee + 255) / 256, 256>>>(ei);
    k_scan<<<1, 1024>>>();
    k_scatter<<<(Ee + 255) / 256, 256>>>(ei, ew);

    const int MB = (Nn + 127) / 128;  // 391 row tiles
    for (int l = 0; l < Ll; l++) {
        // [m | gh] = h @ [W_l | w_hh^T]   (bias [0 | b_hh])
        k_gemm_tc<<<dim3(MB, 4), 256, GEMM_SMEM>>>(
            ph, pBcat + (size_t)l * Hh * 512, pbcat, pmgh, Nn, 512);
        // agg = CSR gather of m[src]*w
        k_agg<<<(Nn * 32 + 255) / 256, 256>>>();
        // gi = agg @ w_ih^T + b_ih
        k_gemm_tc<<<dim3(MB, 3), 256, GEMM_SMEM>>>(pagg, pwihT, b_ih, pgi, Nn, 3 * Hh);
        // h = GRU(agg, h)
        k_gru<<<Nn, Hh>>>();
    }

    k_pool_init<<<(Gg * Hh + 255) / 256, 256>>>();
    k_pool<<<(NH + 255) / 256, 256>>>(batch);
    k_mlp1<<<Gg, Hh>>>(d1w, d1b);
    k_mlp2<<<Gg, 320>>>(d2w, d2b, out);
}

// round 9
// speedup vs baseline: 1.6473x; 1.1234x over previous
#include <cuda_runtime.h>
#include <math.h>

#define Nn 50000
#define Ee 1600000
#define INF_FEATS 64
#define Hh 128
#define Ll 5
#define Gg 512
#define Cc 10

#define AS_STRIDE 68    // 64 + 4 pad  -> A-frag LDS conflict-free (4*lr+lc)
#define BS_STRIDE 136   // 128 + 8 pad -> B-frag LDS conflict-free (8*lc+lr)

// ---------------- scratch (device globals; no allocation allowed) ----------
__device__ float d_h[Nn * Hh];            // node state
__device__ float d_mgh[Nn * 512];         // [m (128) | gh (384)] fused GEMM out
__device__ float d_agg[Nn * Hh];          // gathered messages
__device__ float d_gi[Nn * 3 * Hh];       // agg @ w_ih^T
__device__ float d_wihT[Hh * 3 * Hh];     // w_ih^T [128,384], tf32 pre-rounded
__device__ float d_Bcat[Ll * Hh * 512];   // per-layer [W_l | w_hh^T], tf32 pre-rounded
__device__ float d_bcat[512];             // [0 | b_hh]
__device__ float d_pooled[Gg * Hh];
__device__ float d_hid[Gg * 4 * Hh];
// CSR scratch
__device__ int   d_deg[Nn];
__device__ int   d_rowstart[Nn + 1];
__device__ int   d_cursor[Nn];
__device__ int   d_esrc[Ee];
__device__ float d_ews[Ee];

// ---------------- helpers ---------------------------------------------------
__device__ __forceinline__ float sigmoidf_(float x) {
    return 1.0f / (1.0f + expf(-x));
}

__device__ __forceinline__ unsigned f2tf32(float f) {
    unsigned u;
    asm("cvt.rna.tf32.f32 %0, %1;" : "=r"(u) : "f"(f));
    return u;
}

__device__ __forceinline__ void mma_tf32(float c[4], const unsigned a[4],
                                         const unsigned b[2]) {
    asm volatile(
        "mma.sync.aligned.m16n8k8.row.col.f32.tf32.tf32.f32 "
        "{%0,%1,%2,%3}, {%4,%5,%6,%7}, {%8,%9}, {%0,%1,%2,%3};"
        : "+f"(c[0]), "+f"(c[1]), "+f"(c[2]), "+f"(c[3])
        : "r"(a[0]), "r"(a[1]), "r"(a[2]), "r"(a[3]), "r"(b[0]), "r"(b[1]));
}

// ---------------- setup kernels ---------------------------------------------

__global__ void k_init_h(const float* __restrict__ x) {
    int i = blockIdx.x * blockDim.x + threadIdx.x;
    if (i >= Nn * Hh) return;
    int n = i >> 7, f = i & 127;
    d_h[i] = (f < INF_FEATS) ? x[n * INF_FEATS + f] : 0.0f;
}

// wihT[k][n] = tf32(w_ih[n][k])
__global__ void k_transpose_wih(const float* __restrict__ wih) {
    int i = blockIdx.x * blockDim.x + threadIdx.x;
    if (i >= 3 * Hh * Hh) return;
    int n = i / Hh, k = i % Hh;
    d_wihT[k * (3 * Hh) + n] = __uint_as_float(f2tf32(wih[i]));
}

// Bcat[l][k][c] = tf32( (c<128) ? weight[l][k][c] : w_hh[c-128][k] )
__global__ void k_build_bcat(const float* __restrict__ weight,
                             const float* __restrict__ whh,
                             const float* __restrict__ bhh) {
    int i = blockIdx.x * blockDim.x + threadIdx.x;
    if (i < 512) d_bcat[i] = (i < 128) ? 0.0f : bhh[i - 128];
    if (i >= Ll * Hh * 512) return;
    int l = i / (Hh * 512);
    int r = i % (Hh * 512);
    int k = r / 512, c = r % 512;
    float v = (c < 128) ? weight[(size_t)l * Hh * Hh + k * Hh + c]
                        : whh[(size_t)(c - 128) * Hh + k];
    d_Bcat[i] = __uint_as_float(f2tf32(v));
}

// ---------------- CSR build --------------------------------------------------
__global__ void k_deg_zero() {
    int i = blockIdx.x * blockDim.x + threadIdx.x;
    if (i < Nn) d_deg[i] = 0;
}

__global__ void k_hist(const int* __restrict__ ei) {
    int e = blockIdx.x * blockDim.x + threadIdx.x;
    if (e < Ee) atomicAdd(&d_deg[ei[Ee + e]], 1);
}

__global__ void k_scan() {
    __shared__ int sp[1024];
    const int CH = (Nn + 1023) / 1024;
    int t = threadIdx.x;
    int base = t * CH;
    int s = 0;
    for (int i = 0; i < CH; i++) {
        int idx = base + i;
        if (idx < Nn) s += d_deg[idx];
    }
    sp[t] = s;
    __syncthreads();
    for (int d = 1; d < 1024; d <<= 1) {
        int add = (t >= d) ? sp[t - d] : 0;
        __syncthreads();
        sp[t] += add;
        __syncthreads();
    }
    int off = sp[t] - s;
    for (int i = 0; i < CH; i++) {
        int idx = base + i;
        if (idx < Nn) {
            d_rowstart[idx] = off;
            d_cursor[idx] = off;
            off += d_deg[idx];
        }
    }
    if (t == 1023) d_rowstart[Nn] = off;
}

__global__ void k_scatter(const int* __restrict__ ei, const float* __restrict__ ew) {
    int e = blockIdx.x * blockDim.x + threadIdx.x;
    if (e >= Ee) return;
    int dst = ei[Ee + e];
    int pos = atomicAdd(&d_cursor[dst], 1);
    d_esrc[pos] = ei[e];
    d_ews[pos] = ew[e];
}

// ---------------- GEMM (tf32 tensor cores, K split, 2 CTAs/SM) ---------------
// C[M,Nw] = A[M,128] @ B[128,Nw] (+bias). 128x128 tile, 256 thr, warp 32x64.
// __launch_bounds__(256,2): regs capped at 128 so two CTAs co-reside and
// one CTA's load phase overlaps the other's MMA phase. B is tf32-pre-rounded
// (raw copy, no cvt in the load loop).
__global__ void __launch_bounds__(256, 2)
k_gemm_tc(const float* __restrict__ A, const float* __restrict__ B,
          const float* __restrict__ bias, float* __restrict__ C,
          int M, int Nw) {
    extern __shared__ float sm[];
    float* As = sm;                          // [128][AS_STRIDE] (64 K-cols)
    float* Bs = sm + 128 * AS_STRIDE;        // [64][BS_STRIDE]  (64 K-rows)

    int m0 = blockIdx.x * 128;
    int n0 = blockIdx.y * 128;
    int tid = threadIdx.x;

    int wid = tid >> 5, lane = tid & 31;
    int wm = (wid & 3) * 32;
    int wn = (wid >> 2) * 64;
    int lr = lane >> 2;
    int lc = lane & 3;

    float acc[2][8][4];
    #pragma unroll
    for (int mt = 0; mt < 2; mt++)
        #pragma unroll
        for (int nt = 0; nt < 8; nt++)
            #pragma unroll
            for (int q = 0; q < 4; q++) acc[mt][nt][q] = 0.0f;

    const unsigned* Asu = reinterpret_cast<const unsigned*>(As);
    const unsigned* Bsu = reinterpret_cast<const unsigned*>(Bs);

    #pragma unroll
    for (int s = 0; s < 2; s++) {
        // A slab: rows m0..m0+127, K cols [64s, 64s+64)  (needs cvt)
        #pragma unroll
        for (int i = 0; i < 8; i++) {
            int e = tid + i * 256;            // float4 slot 0..2047
            int r = e >> 4, c4 = e & 15;      // 16 float4 per row
            float4 v = make_float4(0.f, 0.f, 0.f, 0.f);
            if (m0 + r < M)
                v = reinterpret_cast<const float4*>(
                        A + (size_t)(m0 + r) * 128 + s * 64)[c4];
            unsigned* dst = reinterpret_cast<unsigned*>(As + r * AS_STRIDE + c4 * 4);
            dst[0] = f2tf32(v.x); dst[1] = f2tf32(v.y);
            dst[2] = f2tf32(v.z); dst[3] = f2tf32(v.w);
        }
        // B slab: K rows [64s, 64s+64), cols n0..n0+127  (pre-rounded: raw copy)
        #pragma unroll
        for (int i = 0; i < 8; i++) {
            int e = tid + i * 256;
            int r = e >> 5, c4 = e & 31;      // 32 float4 per row
            float4 v = reinterpret_cast<const float4*>(
                           B + (size_t)(s * 64 + r) * Nw + n0)[c4];
            reinterpret_cast<float4*>(Bs + r * BS_STRIDE)[c4] = v;
        }
        __syncthreads();

        #pragma unroll
        for (int k0 = 0; k0 < 64; k0 += 8) {
            unsigned a[2][4], b[8][2];
            #pragma unroll
            for (int mt = 0; mt < 2; mt++) {
                const unsigned* ap = Asu + (wm + mt * 16 + lr) * AS_STRIDE + k0 + lc;
                a[mt][0] = ap[0];
                a[mt][1] = ap[8 * AS_STRIDE];
                a[mt][2] = ap[4];
                a[mt][3] = ap[8 * AS_STRIDE + 4];
            }
            #pragma unroll
            for (int nt = 0; nt < 8; nt++) {
                const unsigned* bp = Bsu + (k0 + lc) * BS_STRIDE + wn + nt * 8 + lr;
                b[nt][0] = bp[0];
                b[nt][1] = bp[4 * BS_STRIDE];
            }
            #pragma unroll
            for (int mt = 0; mt < 2; mt++)
                #pragma unroll
                for (int nt = 0; nt < 8; nt++)
                    mma_tf32(acc[mt][nt], a[mt], b[nt]);
        }
        __syncthreads();
    }

    #pragma unroll
    for (int mt = 0; mt < 2; mt++) {
        #pragma unroll
        for (int nt = 0; nt < 8; nt++) {
            int row = m0 + wm + mt * 16 + lr;
            int col = n0 + wn + nt * 8 + lc * 2;
            float b0 = bias ? bias[col] : 0.0f;
            float b1 = bias ? bias[col + 1] : 0.0f;
            if (row < M) {
                float2 v = make_float2(acc[mt][nt][0] + b0, acc[mt][nt][1] + b1);
                *reinterpret_cast<float2*>(C + (size_t)row * Nw + col) = v;
            }
            if (row + 8 < M) {
                float2 v = make_float2(acc[mt][nt][2] + b0, acc[mt][nt][3] + b1);
                *reinterpret_cast<float2*>(C + (size_t)(row + 8) * Nw + col) = v;
            }
        }
    }
}

// ---------------- CSR aggregation: warp per node ------------------------------
// agg[n] = sum_{e in in(n)} m[src(e)] * w(e);  m = d_mgh[:, 0:128] (stride 512)
__global__ void k_agg() {
    int warp = (blockIdx.x * blockDim.x + threadIdx.x) >> 5;
    if (warp >= Nn) return;
    int lane = threadIdx.x & 31;
    int beg = d_rowstart[warp];
    int end = d_rowstart[warp + 1];
    float4 acc = make_float4(0.f, 0.f, 0.f, 0.f);
    for (int base = beg; base < end; base += 32) {
        int idx = base + lane;
        int sid = 0;
        float w = 0.0f;
        if (idx < end) { sid = d_esrc[idx]; w = d_ews[idx]; }
        int cnt = min(32, end - base);
        #pragma unroll 4
        for (int j = 0; j < cnt; j++) {
            int s = __shfl_sync(0xffffffff, sid, j);
            float wj = __shfl_sync(0xffffffff, w, j);
            float4 v = *reinterpret_cast<const float4*>(
                d_mgh + (size_t)s * 512 + lane * 4);
            acc.x = fmaf(v.x, wj, acc.x);
            acc.y = fmaf(v.y, wj, acc.y);
            acc.z = fmaf(v.z, wj, acc.z);
            acc.w = fmaf(v.w, wj, acc.w);
        }
    }
    *reinterpret_cast<float4*>(d_agg + (size_t)warp * 128 + lane * 4) = acc;
}

// ---------------- GRU --------------------------------------------------------
__global__ void k_gru() {
    int n = blockIdx.x;
    int f = threadIdx.x;
    const float* gi = d_gi + (size_t)n * 384;
    const float* gh = d_mgh + (size_t)n * 512 + 128;
    float r  = sigmoidf_(gi[f] + gh[f]);
    float z  = sigmoidf_(gi[128 + f] + gh[128 + f]);
    float nn = tanhf(gi[256 + f] + r * gh[256 + f]);
    float ho = d_h[(size_t)n * 128 + f];
    d_h[(size_t)n * 128 + f] = (1.0f - z) * nn + z * ho;
}

// ---------------- pooling + MLP ----------------------------------------------
__global__ void k_pool_init() {
    int i = blockIdx.x * blockDim.x + threadIdx.x;
    if (i < Gg * Hh) d_pooled[i] = -INFINITY;
}

__global__ void k_pool(const int* __restrict__ batch) {
    int i = blockIdx.x * blockDim.x + threadIdx.x;
    if (i >= Nn * Hh) return;
    int n = i >> 7, f = i & 127;
    float v = d_h[i];
    int g = batch[n];
    float* addr = &d_pooled[g * Hh + f];
    if (v >= 0.0f)
        atomicMax(reinterpret_cast<int*>(addr), __float_as_int(v));
    else
        atomicMin(reinterpret_cast<unsigned*>(addr), __float_as_uint(v));
}

__global__ void k_mlp1(const float* __restrict__ w, const float* __restrict__ b) {
    __shared__ float p[Hh];
    int g = blockIdx.x;
    p[threadIdx.x] = d_pooled[g * Hh + threadIdx.x];
    __syncthreads();
    for (int o = threadIdx.x; o < 4 * Hh; o += blockDim.x) {
        const float* wr = w + (size_t)o * Hh;
        float s = b[o];
        #pragma unroll 4
        for (int k = 0; k < Hh; k++) s = fmaf(p[k], wr[k], s);
        d_hid[g * 4 * Hh + o] = fmaxf(s, 0.0f);
    }
}

__global__ void k_mlp2(const float* __restrict__ w, const float* __restrict__ b,
                       float* __restrict__ out) {
    __shared__ float hsh[4 * Hh];
    int g = blockIdx.x;
    for (int i = threadIdx.x; i < 4 * Hh; i += blockDim.x)
        hsh[i] = d_hid[g * 4 * Hh + i];
    __syncthreads();
    int warp = threadIdx.x >> 5, lane = threadIdx.x & 31;
    if (warp < Cc) {
        const float* wr = w + (size_t)warp * (4 * Hh);
        float s = 0.0f;
        for (int k = lane; k < 4 * Hh; k += 32) s = fmaf(hsh[k], wr[k], s);
        #pragma unroll
        for (int off = 16; off; off >>= 1)
            s += __shfl_down_sync(0xffffffff, s, off);
        if (lane == 0) out[g * Cc + warp] = s + b[warp];
    }
}

// ---------------- launch ------------------------------------------------------
extern "C" void kernel_launch(void* const* d_in, const int* in_sizes, int n_in,
                              void* d_out, int out_size) {
    const float* x     = (const float*)d_in[0];
    const int*   ei    = (const int*)  d_in[1];
    const int*   batch = (const int*)  d_in[2];
    const float* ew    = (const float*)d_in[3];
    const float* weight= (const float*)d_in[4];
    const float* w_ih  = (const float*)d_in[5];
    const float* w_hh  = (const float*)d_in[6];
    const float* b_ih  = (const float*)d_in[7];
    const float* b_hh  = (const float*)d_in[8];
    const float* d1w   = (const float*)d_in[9];
    const float* d1b   = (const float*)d_in[10];
    const float* d2w   = (const float*)d_in[11];
    const float* d2b   = (const float*)d_in[12];
    float* out = (float*)d_out;

    float *ph, *pmgh, *pagg, *pgi, *pwihT, *pBcat, *pbcat;
    cudaGetSymbolAddress((void**)&ph,    d_h);
    cudaGetSymbolAddress((void**)&pmgh,  d_mgh);
    cudaGetSymbolAddress((void**)&pagg,  d_agg);
    cudaGetSymbolAddress((void**)&pgi,   d_gi);
    cudaGetSymbolAddress((void**)&pwihT, d_wihT);
    cudaGetSymbolAddress((void**)&pBcat, d_Bcat);
    cudaGetSymbolAddress((void**)&pbcat, d_bcat);

    const int GEMM_SMEM = (128 * AS_STRIDE + 64 * BS_STRIDE) * (int)sizeof(float);
    cudaFuncSetAttribute(k_gemm_tc, cudaFuncAttributeMaxDynamicSharedMemorySize,
                         GEMM_SMEM);

    const int NH = Nn * Hh;
    // setup
    k_init_h<<<(NH + 255) / 256, 256>>>(x);
    k_transpose_wih<<<(3 * Hh * Hh + 255) / 256, 256>>>(w_ih);
    k_build_bcat<<<(Ll * Hh * 512 + 255) / 256, 256>>>(weight, w_hh, b_hh);
    // CSR build
    k_deg_zero<<<(Nn + 255) / 256, 256>>>();
    k_hist<<<(Ee + 255) / 256, 256>>>(ei);
    k_scan<<<1, 1024>>>();
    k_scatter<<<(Ee + 255) / 256, 256>>>(ei, ew);

    const int MB = (Nn + 127) / 128;  // 391 row tiles
    for (int l = 0; l < Ll; l++) {
        // [m | gh] = h @ [W_l | w_hh^T]   (bias [0 | b_hh])
        k_gemm_tc<<<dim3(MB, 4), 256, GEMM_SMEM>>>(
            ph, pBcat + (size_t)l * Hh * 512, pbcat, pmgh, Nn, 512);
        // agg = CSR gather of m[src]*w
        k_agg<<<(Nn * 32 + 255) / 256, 256>>>();
        // gi = agg @ w_ih^T + b_ih
        k_gemm_tc<<<dim3(MB, 3), 256, GEMM_SMEM>>>(pagg, pwihT, b_ih, pgi, Nn, 3 * Hh);
        // h = GRU(agg, h)
        k_gru<<<Nn, Hh>>>();
    }

    k_pool_init<<<(Gg * Hh + 255) / 256, 256>>>();
    k_pool<<<(NH + 255) / 256, 256>>>(batch);
    k_mlp1<<<Gg, Hh>>>(d1w, d1b);
    k_mlp2<<<Gg, 320>>>(d2w, d2b, out);
}

// round 10
// speedup vs baseline: 1.9335x; 1.1738x over previous
#include <cuda_runtime.h>
#include <cuda_fp16.h>
#include <math.h>

#define Nn 50000
#define Ee 1600000
#define INF_FEATS 64
#define Hh 128
#define Ll 5
#define Gg 512
#define Cc 10

#define HS 136   // half-stride per smem tile row: 128 + 8 pad -> word stride 68 ≡ 4 (mod 32)
#define WS 68    // word (uint32/half2) stride

// ---------------- scratch (device globals; no allocation allowed) ----------
__device__ float  d_h[Nn * Hh];            // node state
__device__ float  d_mgh[Nn * 512];         // [m (128) | gh (384)] fused GEMM out
__device__ float  d_agg[Nn * Hh];          // gathered messages
__device__ float  d_gi[Nn * 3 * Hh];       // agg @ w_ih^T
__device__ __half d_wih16[3 * Hh * Hh];    // w_ih [384][128] fp16 (n-major)
__device__ __half d_Bcat16[Ll * 512 * Hh]; // per-layer [c][k] fp16 (n-major B^T)
__device__ float  d_bcat[512];             // [0 | b_hh]
__device__ float  d_pooled[Gg * Hh];
__device__ float  d_hid[Gg * 4 * Hh];
// CSR scratch
__device__ int    d_deg[Nn];
__device__ int    d_rowstart[Nn + 1];
__device__ int    d_cursor[Nn];
__device__ int    d_esrc[Ee];
__device__ float  d_ews[Ee];

// ---------------- helpers ---------------------------------------------------
__device__ __forceinline__ float sigmoidf_(float x) {
    return 1.0f / (1.0f + expf(-x));
}

__device__ __forceinline__ void mma_f16(float c[4], const unsigned a[4],
                                        const unsigned b[2]) {
    asm volatile(
        "mma.sync.aligned.m16n8k16.row.col.f32.f16.f16.f32 "
        "{%0,%1,%2,%3}, {%4,%5,%6,%7}, {%8,%9}, {%0,%1,%2,%3};"
        : "+f"(c[0]), "+f"(c[1]), "+f"(c[2]), "+f"(c[3])
        : "r"(a[0]), "r"(a[1]), "r"(a[2]), "r"(a[3]), "r"(b[0]), "r"(b[1]));
}

// ---------------- setup kernels ---------------------------------------------

__global__ void k_init_h(const float* __restrict__ x) {
    int i = blockIdx.x * blockDim.x + threadIdx.x;
    if (i >= Nn * Hh) return;
    int n = i >> 7, f = i & 127;
    d_h[i] = (f < INF_FEATS) ? x[n * INF_FEATS + f] : 0.0f;
}

// wih16[n][k] = fp16(w_ih[n][k])  (identity layout copy-convert)
__global__ void k_prep_wih(const float* __restrict__ wih) {
    int i = blockIdx.x * blockDim.x + threadIdx.x;
    if (i < 3 * Hh * Hh) d_wih16[i] = __float2half_rn(wih[i]);
}

// Bcat16[l][c][k] = fp16( c<128 ? weight[l][k][c] : w_hh[c-128][k] ); bcat
__global__ void k_build_bcat(const float* __restrict__ weight,
                             const float* __restrict__ whh,
                             const float* __restrict__ bhh) {
    int i = blockIdx.x * blockDim.x + threadIdx.x;
    if (i < 512) d_bcat[i] = (i < 128) ? 0.0f : bhh[i - 128];
    if (i >= Ll * 512 * Hh) return;
    int l = i / (512 * Hh);
    int r = i % (512 * Hh);
    int c = r / Hh, k = r % Hh;
    float v = (c < 128) ? weight[(size_t)l * Hh * Hh + k * Hh + c]
                        : whh[(size_t)(c - 128) * Hh + k];
    d_Bcat16[i] = __float2half_rn(v);
}

// ---------------- CSR build --------------------------------------------------
__global__ void k_deg_zero() {
    int i = blockIdx.x * blockDim.x + threadIdx.x;
    if (i < Nn) d_deg[i] = 0;
}

__global__ void k_hist(const int* __restrict__ ei) {
    int e = blockIdx.x * blockDim.x + threadIdx.x;
    if (e < Ee) atomicAdd(&d_deg[ei[Ee + e]], 1);
}

__global__ void k_scan() {
    __shared__ int sp[1024];
    const int CH = (Nn + 1023) / 1024;
    int t = threadIdx.x;
    int base = t * CH;
    int s = 0;
    for (int i = 0; i < CH; i++) {
        int idx = base + i;
        if (idx < Nn) s += d_deg[idx];
    }
    sp[t] = s;
    __syncthreads();
    for (int d = 1; d < 1024; d <<= 1) {
        int add = (t >= d) ? sp[t - d] : 0;
        __syncthreads();
        sp[t] += add;
        __syncthreads();
    }
    int off = sp[t] - s;
    for (int i = 0; i < CH; i++) {
        int idx = base + i;
        if (idx < Nn) {
            d_rowstart[idx] = off;
            d_cursor[idx] = off;
            off += d_deg[idx];
        }
    }
    if (t == 1023) d_rowstart[Nn] = off;
}

__global__ void k_scatter(const int* __restrict__ ei, const float* __restrict__ ew) {
    int e = blockIdx.x * blockDim.x + threadIdx.x;
    if (e >= Ee) return;
    int dst = ei[Ee + e];
    int pos = atomicAdd(&d_cursor[dst], 1);
    d_esrc[pos] = ei[e];
    d_ews[pos] = ew[e];
}

// ---------------- GEMM (fp16 m16n8k16 tensor cores, 2 CTAs/SM) ---------------
// C[M,Nw] = A[M,128] @ B^T  where B16 is n-major [Nw][128] fp16.
// 128x128 block tile, 256 thr = 8 warps (4m x 2n); warp tile 32x64.
// A converted fp32->fp16 on smem load; B raw-copied (pre-converted at setup).
__global__ void __launch_bounds__(256, 2)
k_gemm_h(const float* __restrict__ A, const __half* __restrict__ B16,
         const float* __restrict__ bias, float* __restrict__ C,
         int M, int Nw) {
    extern __shared__ __half smh[];
    __half* Ash = smh;               // [128][HS]  (m-major, k cols)
    __half* Bsh = smh + 128 * HS;    // [128][HS]  (n-major, k cols)

    int m0 = blockIdx.x * 128;
    int n0 = blockIdx.y * 128;
    int tid = threadIdx.x;

    // A tile: 128 rows x 128 k (fp32 -> fp16).  4096 float4 slots, 16 iters.
    #pragma unroll
    for (int i = 0; i < 16; i++) {
        int e = tid + i * 256;
        int r = e >> 5, c4 = e & 31;          // 32 float4 per row
        float4 v = make_float4(0.f, 0.f, 0.f, 0.f);
        if (m0 + r < M)
            v = reinterpret_cast<const float4*>(A + (size_t)(m0 + r) * 128)[c4];
        __half2* dst = reinterpret_cast<__half2*>(Ash + r * HS + c4 * 4);
        dst[0] = __floats2half2_rn(v.x, v.y);
        dst[1] = __floats2half2_rn(v.z, v.w);
    }
    // B tile: 128 n-rows x 128 k (fp16 raw).  2048 float4 slots (8 halfs), 8 iters.
    #pragma unroll
    for (int i = 0; i < 8; i++) {
        int e = tid + i * 256;
        int r = e >> 4, c4 = e & 15;          // 16 float4 per row
        float4 v = reinterpret_cast<const float4*>(B16 + (size_t)(n0 + r) * 128)[c4];
        reinterpret_cast<float4*>(Bsh + r * HS)[c4] = v;
    }
    __syncthreads();

    int wid = tid >> 5, lane = tid & 31;
    int wm = (wid & 3) * 32;
    int wn = (wid >> 2) * 64;
    int lr = lane >> 2;       // groupID
    int lc = lane & 3;        // threadID_in_group

    float acc[2][8][4];
    #pragma unroll
    for (int mt = 0; mt < 2; mt++)
        #pragma unroll
        for (int nt = 0; nt < 8; nt++)
            #pragma unroll
            for (int q = 0; q < 4; q++) acc[mt][nt][q] = 0.0f;

    const unsigned* Asu = reinterpret_cast<const unsigned*>(Ash);
    const unsigned* Bsu = reinterpret_cast<const unsigned*>(Bsh);

    // 8 k-steps of K=16 (word offset kh = 8 per step)
    #pragma unroll
    for (int ks = 0; ks < 8; ks++) {
        int kh = ks * 8;                       // half2-word offset in row
        unsigned a[2][4], b[8][2];
        #pragma unroll
        for (int mt = 0; mt < 2; mt++) {
            const unsigned* ap = Asu + (wm + mt * 16 + lr) * WS + kh + lc;
            a[mt][0] = ap[0];            // row lr,    k 2lc..2lc+1
            a[mt][1] = ap[8 * WS];       // row lr+8,  k 2lc..
            a[mt][2] = ap[4];            // row lr,    k 8+2lc..
            a[mt][3] = ap[8 * WS + 4];   // row lr+8,  k 8+2lc..
        }
        #pragma unroll
        for (int nt = 0; nt < 8; nt++) {
            const unsigned* bp = Bsu + (wn + nt * 8 + lr) * WS + kh + lc;
            b[nt][0] = bp[0];            // col lr, k 2lc..2lc+1
            b[nt][1] = bp[4];            // col lr, k 8+2lc..
        }
        #pragma unroll
        for (int mt = 0; mt < 2; mt++)
            #pragma unroll
            for (int nt = 0; nt < 8; nt++)
                mma_f16(acc[mt][nt], a[mt], b[nt]);
    }

    #pragma unroll
    for (int mt = 0; mt < 2; mt++) {
        #pragma unroll
        for (int nt = 0; nt < 8; nt++) {
            int row = m0 + wm + mt * 16 + lr;
            int col = n0 + wn + nt * 8 + lc * 2;
            float b0 = bias ? bias[col] : 0.0f;
            float b1 = bias ? bias[col + 1] : 0.0f;
            if (row < M) {
                float2 v = make_float2(acc[mt][nt][0] + b0, acc[mt][nt][1] + b1);
                *reinterpret_cast<float2*>(C + (size_t)row * Nw + col) = v;
            }
            if (row + 8 < M) {
                float2 v = make_float2(acc[mt][nt][2] + b0, acc[mt][nt][3] + b1);
                *reinterpret_cast<float2*>(C + (size_t)(row + 8) * Nw + col) = v;
            }
        }
    }
}

// ---------------- CSR aggregation: warp per node ------------------------------
// agg[n] = sum_{e in in(n)} m[src(e)] * w(e);  m = d_mgh[:, 0:128] (stride 512)
__global__ void k_agg() {
    int warp = (blockIdx.x * blockDim.x + threadIdx.x) >> 5;
    if (warp >= Nn) return;
    int lane = threadIdx.x & 31;
    int beg = d_rowstart[warp];
    int end = d_rowstart[warp + 1];
    float4 acc = make_float4(0.f, 0.f, 0.f, 0.f);
    for (int base = beg; base < end; base += 32) {
        int idx = base + lane;
        int sid = 0;
        float w = 0.0f;
        if (idx < end) { sid = d_esrc[idx]; w = d_ews[idx]; }
        int cnt = min(32, end - base);
        #pragma unroll 4
        for (int j = 0; j < cnt; j++) {
            int s = __shfl_sync(0xffffffff, sid, j);
            float wj = __shfl_sync(0xffffffff, w, j);
            float4 v = *reinterpret_cast<const float4*>(
                d_mgh + (size_t)s * 512 + lane * 4);
            acc.x = fmaf(v.x, wj, acc.x);
            acc.y = fmaf(v.y, wj, acc.y);
            acc.z = fmaf(v.z, wj, acc.z);
            acc.w = fmaf(v.w, wj, acc.w);
        }
    }
    *reinterpret_cast<float4*>(d_agg + (size_t)warp * 128 + lane * 4) = acc;
}

// ---------------- GRU --------------------------------------------------------
__global__ void k_gru() {
    int n = blockIdx.x;
    int f = threadIdx.x;
    const float* gi = d_gi + (size_t)n * 384;
    const float* gh = d_mgh + (size_t)n * 512 + 128;
    float r  = sigmoidf_(gi[f] + gh[f]);
    float z  = sigmoidf_(gi[128 + f] + gh[128 + f]);
    float nn = tanhf(gi[256 + f] + r * gh[256 + f]);
    float ho = d_h[(size_t)n * 128 + f];
    d_h[(size_t)n * 128 + f] = (1.0f - z) * nn + z * ho;
}

// ---------------- pooling + MLP ----------------------------------------------
__global__ void k_pool_init() {
    int i = blockIdx.x * blockDim.x + threadIdx.x;
    if (i < Gg * Hh) d_pooled[i] = -INFINITY;
}

__global__ void k_pool(const int* __restrict__ batch) {
    int i = blockIdx.x * blockDim.x + threadIdx.x;
    if (i >= Nn * Hh) return;
    int n = i >> 7, f = i & 127;
    float v = d_h[i];
    int g = batch[n];
    float* addr = &d_pooled[g * Hh + f];
    if (v >= 0.0f)
        atomicMax(reinterpret_cast<int*>(addr), __float_as_int(v));
    else
        atomicMin(reinterpret_cast<unsigned*>(addr), __float_as_uint(v));
}

__global__ void k_mlp1(const float* __restrict__ w, const float* __restrict__ b) {
    __shared__ float p[Hh];
    int g = blockIdx.x;
    p[threadIdx.x] = d_pooled[g * Hh + threadIdx.x];
    __syncthreads();
    for (int o = threadIdx.x; o < 4 * Hh; o += blockDim.x) {
        const float* wr = w + (size_t)o * Hh;
        float s = b[o];
        #pragma unroll 4
        for (int k = 0; k < Hh; k++) s = fmaf(p[k], wr[k], s);
        d_hid[g * 4 * Hh + o] = fmaxf(s, 0.0f);
    }
}

__global__ void k_mlp2(const float* __restrict__ w, const float* __restrict__ b,
                       float* __restrict__ out) {
    __shared__ float hsh[4 * Hh];
    int g = blockIdx.x;
    for (int i = threadIdx.x; i < 4 * Hh; i += blockDim.x)
        hsh[i] = d_hid[g * 4 * Hh + i];
    __syncthreads();
    int warp = threadIdx.x >> 5, lane = threadIdx.x & 31;
    if (warp < Cc) {
        const float* wr = w + (size_t)warp * (4 * Hh);
        float s = 0.0f;
        for (int k = lane; k < 4 * Hh; k += 32) s = fmaf(hsh[k], wr[k], s);
        #pragma unroll
        for (int off = 16; off; off >>= 1)
            s += __shfl_down_sync(0xffffffff, s, off);
        if (lane == 0) out[g * Cc + warp] = s + b[warp];
    }
}

// ---------------- launch ------------------------------------------------------
extern "C" void kernel_launch(void* const* d_in, const int* in_sizes, int n_in,
                              void* d_out, int out_size) {
    const float* x     = (const float*)d_in[0];
    const int*   ei    = (const int*)  d_in[1];
    const int*   batch = (const int*)  d_in[2];
    const float* ew    = (const float*)d_in[3];
    const float* weight= (const float*)d_in[4];
    const float* w_ih  = (const float*)d_in[5];
    const float* w_hh  = (const float*)d_in[6];
    const float* b_ih  = (const float*)d_in[7];
    const float* b_hh  = (const float*)d_in[8];
    const float* d1w   = (const float*)d_in[9];
    const float* d1b   = (const float*)d_in[10];
    const float* d2w   = (const float*)d_in[11];
    const float* d2b   = (const float*)d_in[12];
    float* out = (float*)d_out;

    float  *ph, *pmgh, *pagg, *pgi, *pbcat;
    __half *pwih16, *pBcat16;
    cudaGetSymbolAddress((void**)&ph,      d_h);
    cudaGetSymbolAddress((void**)&pmgh,    d_mgh);
    cudaGetSymbolAddress((void**)&pagg,    d_agg);
    cudaGetSymbolAddress((void**)&pgi,     d_gi);
    cudaGetSymbolAddress((void**)&pwih16,  d_wih16);
    cudaGetSymbolAddress((void**)&pBcat16, d_Bcat16);
    cudaGetSymbolAddress((void**)&pbcat,   d_bcat);

    const int GEMM_SMEM = 2 * 128 * HS * (int)sizeof(__half);   // 69.6 KB
    cudaFuncSetAttribute(k_gemm_h, cudaFuncAttributeMaxDynamicSharedMemorySize,
                         GEMM_SMEM);

    const int NH = Nn * Hh;
    // setup
    k_init_h<<<(NH + 255) / 256, 256>>>(x);
    k_prep_wih<<<(3 * Hh * Hh + 255) / 256, 256>>>(w_ih);
    k_build_bcat<<<(Ll * 512 * Hh + 255) / 256, 256>>>(weight, w_hh, b_hh);
    // CSR build
    k_deg_zero<<<(Nn + 255) / 256, 256>>>();
    k_hist<<<(Ee + 255) / 256, 256>>>(ei);
    k_scan<<<1, 1024>>>();
    k_scatter<<<(Ee + 255) / 256, 256>>>(ei, ew);

    const int MB = (Nn + 127) / 128;  // 391 row tiles
    for (int l = 0; l < Ll; l++) {
        // [m | gh] = h @ [W_l | w_hh^T]   (bias [0 | b_hh])
        k_gemm_h<<<dim3(MB, 4), 256, GEMM_SMEM>>>(
            ph, pBcat16 + (size_t)l * 512 * Hh, pbcat, pmgh, Nn, 512);
        // agg = CSR gather of m[src]*w
        k_agg<<<(Nn * 32 + 255) / 256, 256>>>();
        // gi = agg @ w_ih^T + b_ih
        k_gemm_h<<<dim3(MB, 3), 256, GEMM_SMEM>>>(pagg, pwih16, b_ih, pgi, Nn, 3 * Hh);
        // h = GRU(agg, h)
        k_gru<<<Nn, Hh>>>();
    }

    k_pool_init<<<(Gg * Hh + 255) / 256, 256>>>();
    k_pool<<<(NH + 255) / 256, 256>>>(batch);
    k_mlp1<<<Gg, Hh>>>(d1w, d1b);
    k_mlp2<<<Gg, 320>>>(d2w, d2b, out);
}